// round 16
// baseline (speedup 1.0000x reference)
#include <cuda_runtime.h>
#include <math.h>

#define BATCH   2048
#define NCH     128
#define TOTDIM  200

// Flattened offsets of the per-l A blocks: sizes 1,9,25,49,81 -> total 165
#define AOFF0 0
#define AOFF1 1
#define AOFF2 10
#define AOFF3 35
#define AOFF4 84
#define ATOT  165

struct AParams { float A[ATOT]; };   // constant Wigner A(l) blocks (kernel param)

// ---------------------------------------------------------------------------
// Host-side computation of the constant A(l) matrices (exact port of the
// Python reference, fp64). Runs at capture time only — zero replay cost.
// ---------------------------------------------------------------------------
static double h_fact(int n) {
    double r = 1.0;
    for (int k = 2; k <= n; ++k) r *= (double)k;
    return r;
}

static void host_compute_A(AParams& P) {
    const double PI = 3.14159265358979323846;
    const double IS2 = 0.70710678118654752440;
    int off = 0;
    for (int l = 0; l < 5; ++l) {
        int d = 2 * l + 1;
        double sd[9][9];
        double cb = cos(-PI / 4.0), sb = sin(-PI / 4.0);
        for (int mp = -l; mp <= l; ++mp) {
            for (int m = -l; m <= l; ++m) {
                double pref = sqrt(h_fact(l + mp) * h_fact(l - mp) *
                                   h_fact(l + m) * h_fact(l - m));
                double tot = 0.0;
                int s0 = (m - mp > 0) ? (m - mp) : 0;
                int s1 = (l + m < l - mp) ? (l + m) : (l - mp);
                for (int s = s0; s <= s1; ++s) {
                    double den = h_fact(l + m - s) * h_fact(s) *
                                 h_fact(mp - m + s) * h_fact(l - mp - s);
                    double sgn = ((mp - m + s) & 1) ? -1.0 : 1.0;
                    tot += sgn / den * pow(cb, 2 * l + m - mp - 2 * s)
                                     * pow(sb, mp - m + 2 * s);
                }
                sd[mp + l][m + l] = pref * tot;
            }
        }
        double DcRe[9][9], DcIm[9][9];
        for (int p = 0; p < d; ++p) {
            for (int q = 0; q < d; ++q) {
                double ang = (p - l) * (PI / 2.0) - (q - l) * (PI / 2.0);
                DcRe[p][q] = cos(ang) * sd[p][q];
                DcIm[p][q] = sin(ang) * sd[p][q];
            }
        }
        double URe[9][9] = {}, UIm[9][9] = {};
        URe[l][l] = 1.0;
        for (int m = 1; m <= l; ++m) {
            double sgn = (m & 1) ? -1.0 : 1.0;
            URe[l + m][l + m] = sgn * IS2;
            URe[l + m][l - m] = IS2;
            UIm[l - m][l - m] = IS2;
            UIm[l - m][l + m] = -sgn * IS2;
        }
        double TRe[9][9], TIm[9][9];
        for (int i = 0; i < d; ++i) {
            for (int q = 0; q < d; ++q) {
                double re = 0.0, im = 0.0;
                for (int p = 0; p < d; ++p) {
                    re += URe[i][p] * DcRe[p][q] - UIm[i][p] * DcIm[p][q];
                    im += URe[i][p] * DcIm[p][q] + UIm[i][p] * DcRe[p][q];
                }
                TRe[i][q] = re; TIm[i][q] = im;
            }
        }
        for (int i = 0; i < d; ++i) {
            for (int j = 0; j < d; ++j) {
                double a = 0.0;
                for (int q = 0; q < d; ++q)
                    a += TRe[i][q] * URe[j][q] + TIm[i][q] * UIm[j][q];
                P.A[off + i * d + j] = (float)a;
            }
        }
        off += d * d;
    }
}

// ---------------------------------------------------------------------------
// Z-rotation coefficient helpers on a per-batch global sincos row (10 floats:
// m=0..4 x {sin,cos}).
// ---------------------------------------------------------------------------
__device__ __forceinline__ float zcg(const float* g, int k, int L) {
    int am = (k >= L) ? (k - L) : (L - k);
    return __ldg(g + am * 2 + 1);
}
__device__ __forceinline__ float zsg(const float* g, int k, int L) {
    int mm = k - L;
    if (mm > 0) return  __ldg(g + mm * 2);
    if (mm < 0) return -__ldg(g - mm * 2);
    return 0.0f;
}

// One entry of D = Za * A * Zb * A^T * Zg, computed from the constant-bank A
// block and global (L1/L2-resident) sincos rows. No smem inputs.
template <int L>
__device__ __forceinline__ float build_entry_g(const float* alB, const float* beB,
                                               const float* gaB,
                                               const float* A, int e) {
    constexpr int D = 2 * L + 1;
    const int i = e / D, j = e - i * D;
    const int ri = D - 1 - i, rj = D - 1 - j;
    const float cg = zcg(gaB, j, L);
    const float sg = zsg(gaB, rj, L);
    float t3 = 0.0f, t3r = 0.0f;
#pragma unroll
    for (int k = 0; k < D; ++k) {
        const int rk = D - 1 - k;
        float T1k  = A[j * D + k]  * cg + A[rj * D + k]  * sg;
        float T1rk = A[j * D + rk] * cg + A[rj * D + rk] * sg;
        float T2k = zcg(beB, k, L) * T1k + zsg(beB, k, L) * T1rk;
        t3  = fmaf(A[i * D + k],  T2k, t3);
        t3r = fmaf(A[ri * D + k], T2k, t3r);
    }
    return zcg(alB, i, L) * t3 + zsg(alB, i, L) * t3r;
}

// ---------------------------------------------------------------------------
// Per-segment processing (single l) with exactly ONE barrier:
//   builders (tid < D*D) compute their D entry (ldg sincos + const-bank A),
//   everyone issues x loads (evict-first), builders publish to smem, one
//   sync, FMA + streaming store.
// ---------------------------------------------------------------------------
template <int L>
__device__ __forceinline__ void seg_full(const float* __restrict__ x,
                                         float* __restrict__ y,
                                         const float* __restrict__ Ablk,
                                         const float* alB, const float* beB,
                                         const float* gaB, float* DmS,
                                         int b, int OFF, int tid) {
    constexpr int D  = 2 * L + 1;
    constexpr int DD = D * D;
    const int mult = tid >> 5;
    const int lane = tid & 31;
    const size_t base = ((size_t)b * TOTDIM + OFF + mult * D) * NCH;
    const float4* xp = (const float4*)(x + base);
    float4* yp = (float4*)(y + base);

    // Builders start their sincos loads / ALU first (program order).
    float dval = 0.0f;
    if (tid < DD) dval = build_entry_g<L>(alB, beB, gaB, Ablk, tid);

    // Pre-issue global x loads (in flight across the barrier).
    float4 xr[D];
#pragma unroll
    for (int j = 0; j < D; ++j) xr[j] = __ldcs(xp + j * 32 + lane);

    if (tid < DD) DmS[tid] = dval;
    __syncthreads();

#pragma unroll
    for (int i = 0; i < D; ++i) {
        float4 acc = { 0.f, 0.f, 0.f, 0.f };
#pragma unroll
        for (int j = 0; j < D; ++j) {
            float c = DmS[i * D + j];
            acc.x = fmaf(c, xr[j].x, acc.x);
            acc.y = fmaf(c, xr[j].y, acc.y);
            acc.z = fmaf(c, xr[j].z, acc.z);
            acc.w = fmaf(c, xr[j].w, acc.w);
        }
        __stcs(yp + i * 32 + lane, acc);
    }
}

// ---------------------------------------------------------------------------
// Kernel: 1D grid of 6144 blocks, 256 threads.
//   type = bx % 3 : 0 -> l0+l1+l2 (72 rows, MLP 9)
//                   1 -> l3       (56 rows, MLP 7)
//                   2 -> l4       (72 rows, MLP 9)
//   b    = bx / 3
// Uniform per-block work (72/56/72 rows) keeps every wave balanced; the
// light irreps now front-batch 9 loads like the heavy ones.
// ---------------------------------------------------------------------------
__global__ void __launch_bounds__(256)
fused_kernel(const AParams Ap,
             const float* __restrict__ x,
             const float* __restrict__ al,
             const float* __restrict__ be,
             const float* __restrict__ ga,
             float* __restrict__ y) {
    const int bx   = blockIdx.x;
    const int b    = bx / 3;
    const int type = bx - b * 3;
    const int tid  = threadIdx.x;

    __shared__ float DmS[81];

    const float* alB = al + b * 10;
    const float* beB = be + b * 10;
    const float* gaB = ga + b * 10;

    switch (type) {
        case 0: {  // l=0 (rows 0..7), l=1 (rows 8..31), l=2 (rows 32..71)
            const int mult = tid >> 5;
            const int lane = tid & 31;
            const size_t base0 = ((size_t)b * TOTDIM + mult) * NCH;
            const size_t base1 = ((size_t)b * TOTDIM + 8  + mult * 3) * NCH;
            const size_t base2 = ((size_t)b * TOTDIM + 32 + mult * 5) * NCH;
            const float4* xp0 = (const float4*)(x + base0);
            const float4* xp1 = (const float4*)(x + base1);
            const float4* xp2 = (const float4*)(x + base2);

            // builders first: DmS layout [0]=l0, [1..9]=l1, [10..34]=l2
            float dval = 0.0f;
            if (tid == 0)       dval = build_entry_g<0>(alB, beB, gaB, Ap.A + AOFF0, 0);
            else if (tid < 10)  dval = build_entry_g<1>(alB, beB, gaB, Ap.A + AOFF1, tid - 1);
            else if (tid < 35)  dval = build_entry_g<2>(alB, beB, gaB, Ap.A + AOFF2, tid - 10);

            // pre-issue all 9 x loads (in flight across the barrier)
            float4 x0 = __ldcs(xp0 + lane);
            float4 xr1[3];
#pragma unroll
            for (int j = 0; j < 3; ++j) xr1[j] = __ldcs(xp1 + j * 32 + lane);
            float4 xr2[5];
#pragma unroll
            for (int j = 0; j < 5; ++j) xr2[j] = __ldcs(xp2 + j * 32 + lane);

            if (tid < 35) DmS[tid] = dval;
            __syncthreads();

            {   // l=0
                float c = DmS[0];
                float4* yp0 = (float4*)(y + base0);
                float4 r = { c * x0.x, c * x0.y, c * x0.z, c * x0.w };
                __stcs(yp0 + lane, r);
            }
            {   // l=1
                float4* yp1 = (float4*)(y + base1);
#pragma unroll
                for (int i = 0; i < 3; ++i) {
                    float4 acc = { 0.f, 0.f, 0.f, 0.f };
#pragma unroll
                    for (int j = 0; j < 3; ++j) {
                        float c = DmS[1 + i * 3 + j];
                        acc.x = fmaf(c, xr1[j].x, acc.x);
                        acc.y = fmaf(c, xr1[j].y, acc.y);
                        acc.z = fmaf(c, xr1[j].z, acc.z);
                        acc.w = fmaf(c, xr1[j].w, acc.w);
                    }
                    __stcs(yp1 + i * 32 + lane, acc);
                }
            }
            {   // l=2
                float4* yp2 = (float4*)(y + base2);
#pragma unroll
                for (int i = 0; i < 5; ++i) {
                    float4 acc = { 0.f, 0.f, 0.f, 0.f };
#pragma unroll
                    for (int j = 0; j < 5; ++j) {
                        float c = DmS[10 + i * 5 + j];
                        acc.x = fmaf(c, xr2[j].x, acc.x);
                        acc.y = fmaf(c, xr2[j].y, acc.y);
                        acc.z = fmaf(c, xr2[j].z, acc.z);
                        acc.w = fmaf(c, xr2[j].w, acc.w);
                    }
                    __stcs(yp2 + i * 32 + lane, acc);
                }
            }
            break;
        }
        case 1: seg_full<3>(x, y, Ap.A + AOFF3, alB, beB, gaB, DmS, b, 72,  tid); break;
        default: seg_full<4>(x, y, Ap.A + AOFF4, alB, beB, gaB, DmS, b, 128, tid); break;
    }
}

// ---------------------------------------------------------------------------
extern "C" void kernel_launch(void* const* d_in, const int* in_sizes, int n_in,
                              void* d_out, int out_size) {
    (void)in_sizes; (void)n_in; (void)out_size;
    const float* x  = (const float*)d_in[0];  // (2048, 200, 128) f32
    const float* al = (const float*)d_in[1];  // (2048, 5, 2) f32
    const float* be = (const float*)d_in[2];
    const float* ga = (const float*)d_in[3];
    float* y = (float*)d_out;

    AParams P;
    host_compute_A(P);   // host-side, capture-time only

    fused_kernel<<<BATCH * 3, 256>>>(P, x, al, be, ga, y);
}

// round 17
// speedup vs baseline: 1.0010x; 1.0010x over previous
#include <cuda_runtime.h>
#include <math.h>

#define BATCH   2048
#define NCH     128
#define TOTDIM  200

// Flattened offsets of the per-l A blocks: sizes 1,9,25,49,81 -> total 165
#define AOFF0 0
#define AOFF1 1
#define AOFF2 10
#define AOFF3 35
#define AOFF4 84
#define ATOT  165

struct AParams { float A[ATOT]; };   // constant Wigner A(l) blocks (kernel param)

// ---------------------------------------------------------------------------
// Host-side computation of the constant A(l) matrices (exact port of the
// Python reference, fp64). Runs at capture time only — zero replay cost.
// ---------------------------------------------------------------------------
static double h_fact(int n) {
    double r = 1.0;
    for (int k = 2; k <= n; ++k) r *= (double)k;
    return r;
}

static void host_compute_A(AParams& P) {
    const double PI = 3.14159265358979323846;
    const double IS2 = 0.70710678118654752440;
    int off = 0;
    for (int l = 0; l < 5; ++l) {
        int d = 2 * l + 1;
        double sd[9][9];
        double cb = cos(-PI / 4.0), sb = sin(-PI / 4.0);
        for (int mp = -l; mp <= l; ++mp) {
            for (int m = -l; m <= l; ++m) {
                double pref = sqrt(h_fact(l + mp) * h_fact(l - mp) *
                                   h_fact(l + m) * h_fact(l - m));
                double tot = 0.0;
                int s0 = (m - mp > 0) ? (m - mp) : 0;
                int s1 = (l + m < l - mp) ? (l + m) : (l - mp);
                for (int s = s0; s <= s1; ++s) {
                    double den = h_fact(l + m - s) * h_fact(s) *
                                 h_fact(mp - m + s) * h_fact(l - mp - s);
                    double sgn = ((mp - m + s) & 1) ? -1.0 : 1.0;
                    tot += sgn / den * pow(cb, 2 * l + m - mp - 2 * s)
                                     * pow(sb, mp - m + 2 * s);
                }
                sd[mp + l][m + l] = pref * tot;
            }
        }
        double DcRe[9][9], DcIm[9][9];
        for (int p = 0; p < d; ++p) {
            for (int q = 0; q < d; ++q) {
                double ang = (p - l) * (PI / 2.0) - (q - l) * (PI / 2.0);
                DcRe[p][q] = cos(ang) * sd[p][q];
                DcIm[p][q] = sin(ang) * sd[p][q];
            }
        }
        double URe[9][9] = {}, UIm[9][9] = {};
        URe[l][l] = 1.0;
        for (int m = 1; m <= l; ++m) {
            double sgn = (m & 1) ? -1.0 : 1.0;
            URe[l + m][l + m] = sgn * IS2;
            URe[l + m][l - m] = IS2;
            UIm[l - m][l - m] = IS2;
            UIm[l - m][l + m] = -sgn * IS2;
        }
        double TRe[9][9], TIm[9][9];
        for (int i = 0; i < d; ++i) {
            for (int q = 0; q < d; ++q) {
                double re = 0.0, im = 0.0;
                for (int p = 0; p < d; ++p) {
                    re += URe[i][p] * DcRe[p][q] - UIm[i][p] * DcIm[p][q];
                    im += URe[i][p] * DcIm[p][q] + UIm[i][p] * DcRe[p][q];
                }
                TRe[i][q] = re; TIm[i][q] = im;
            }
        }
        for (int i = 0; i < d; ++i) {
            for (int j = 0; j < d; ++j) {
                double a = 0.0;
                for (int q = 0; q < d; ++q)
                    a += TRe[i][q] * URe[j][q] + TIm[i][q] * UIm[j][q];
                P.A[off + i * d + j] = (float)a;
            }
        }
        off += d * d;
    }
}

// ---------------------------------------------------------------------------
// Z-rotation coefficient helpers on a per-batch global sincos row (10 floats:
// m=0..4 x {sin,cos}).
// ---------------------------------------------------------------------------
__device__ __forceinline__ float zcg(const float* g, int k, int L) {
    int am = (k >= L) ? (k - L) : (L - k);
    return __ldg(g + am * 2 + 1);
}
__device__ __forceinline__ float zsg(const float* g, int k, int L) {
    int mm = k - L;
    if (mm > 0) return  __ldg(g + mm * 2);
    if (mm < 0) return -__ldg(g - mm * 2);
    return 0.0f;
}

// One entry of D = Za * A * Zb * A^T * Zg, computed from the constant-bank A
// block and global (L1/L2-resident) sincos rows. No smem inputs.
template <int L>
__device__ __forceinline__ float build_entry_g(const float* alB, const float* beB,
                                               const float* gaB,
                                               const float* A, int e) {
    constexpr int D = 2 * L + 1;
    const int i = e / D, j = e - i * D;
    const int ri = D - 1 - i, rj = D - 1 - j;
    const float cg = zcg(gaB, j, L);
    const float sg = zsg(gaB, rj, L);
    float t3 = 0.0f, t3r = 0.0f;
#pragma unroll
    for (int k = 0; k < D; ++k) {
        const int rk = D - 1 - k;
        float T1k  = A[j * D + k]  * cg + A[rj * D + k]  * sg;
        float T1rk = A[j * D + rk] * cg + A[rj * D + rk] * sg;
        float T2k = zcg(beB, k, L) * T1k + zsg(beB, k, L) * T1rk;
        t3  = fmaf(A[i * D + k],  T2k, t3);
        t3r = fmaf(A[ri * D + k], T2k, t3r);
    }
    return zcg(alB, i, L) * t3 + zsg(alB, i, L) * t3r;
}

// component select from a float4 (constant-folds under full unroll)
__device__ __forceinline__ float comp4(const float4& v, int k) {
    return k == 0 ? v.x : k == 1 ? v.y : k == 2 ? v.z : v.w;
}

// ---------------------------------------------------------------------------
// Per-segment processing (single l) with exactly ONE barrier. D rows are
// stored padded to 16B (stride PD) so the FMA loop fetches each coefficient
// row with 2-3 LDS.128 instead of D scalar LDS.
// ---------------------------------------------------------------------------
template <int L>
__device__ __forceinline__ void seg_full(const float* __restrict__ x,
                                         float* __restrict__ y,
                                         const float* __restrict__ Ablk,
                                         const float* alB, const float* beB,
                                         const float* gaB,
                                         float* DmS, const float4* DmS4,
                                         int b, int OFF, int tid) {
    constexpr int D  = 2 * L + 1;
    constexpr int DD = D * D;
    constexpr int PD = (D + 3) & ~3;          // padded row stride (floats)
    const int mult = tid >> 5;
    const int lane = tid & 31;
    const size_t base = ((size_t)b * TOTDIM + OFF + mult * D) * NCH;
    const float4* xp = (const float4*)(x + base);
    float4* yp = (float4*)(y + base);

    // Builders start their sincos loads / ALU first (program order).
    float dval = 0.0f;
    if (tid < DD) dval = build_entry_g<L>(alB, beB, gaB, Ablk, tid);

    // Pre-issue global x loads (in flight across the barrier).
    float4 xr[D];
#pragma unroll
    for (int j = 0; j < D; ++j) xr[j] = __ldcs(xp + j * 32 + lane);

    if (tid < DD) {
        const int i = tid / D, j = tid - i * D;
        DmS[i * PD + j] = dval;
    }
    __syncthreads();

#pragma unroll
    for (int i = 0; i < D; ++i) {
        // vector-fetch coefficient row i (padding lanes unused)
        float4 v0 = DmS4[i * (PD / 4) + 0];
        float4 v1 = (PD > 4) ? DmS4[i * (PD / 4) + 1] : v0;
        float4 v2 = (PD > 8) ? DmS4[i * (PD / 4) + 2] : v0;
        float4 acc = { 0.f, 0.f, 0.f, 0.f };
#pragma unroll
        for (int j = 0; j < D; ++j) {
            float c = (j < 4) ? comp4(v0, j) : (j < 8) ? comp4(v1, j - 4)
                                             : comp4(v2, j - 8);
            acc.x = fmaf(c, xr[j].x, acc.x);
            acc.y = fmaf(c, xr[j].y, acc.y);
            acc.z = fmaf(c, xr[j].z, acc.z);
            acc.w = fmaf(c, xr[j].w, acc.w);
        }
        __stcs(yp + i * 32 + lane, acc);
    }
}

// ---------------------------------------------------------------------------
// Kernel: 1D grid of 6144 blocks, 256 threads.
//   type = bx % 3 : 0 -> l0+l1+l2 (72 rows, MLP 9)
//                   1 -> l3       (56 rows, MLP 7)
//                   2 -> l4       (72 rows, MLP 9)
// Padded DmS layout (floats):
//   type 0: l0 at [0]; l1 row i at [4+4i]; l2 row i at [16+8i]   (56 used)
//   type 1: row i at [8i]   (PD=8,  56 used)
//   type 2: row i at [12i]  (PD=12, 108 used)
// ---------------------------------------------------------------------------
__global__ void __launch_bounds__(256)
fused_kernel(const AParams Ap,
             const float* __restrict__ x,
             const float* __restrict__ al,
             const float* __restrict__ be,
             const float* __restrict__ ga,
             float* __restrict__ y) {
    const int bx   = blockIdx.x;
    const int b    = bx / 3;
    const int type = bx - b * 3;
    const int tid  = threadIdx.x;

    __shared__ __align__(16) float DmS[108];
    const float4* DmS4 = (const float4*)DmS;

    const float* alB = al + b * 10;
    const float* beB = be + b * 10;
    const float* gaB = ga + b * 10;

    switch (type) {
        case 0: {  // l=0 (rows 0..7), l=1 (rows 8..31), l=2 (rows 32..71)
            const int mult = tid >> 5;
            const int lane = tid & 31;
            const size_t base0 = ((size_t)b * TOTDIM + mult) * NCH;
            const size_t base1 = ((size_t)b * TOTDIM + 8  + mult * 3) * NCH;
            const size_t base2 = ((size_t)b * TOTDIM + 32 + mult * 5) * NCH;
            const float4* xp0 = (const float4*)(x + base0);
            const float4* xp1 = (const float4*)(x + base1);
            const float4* xp2 = (const float4*)(x + base2);

            // builders first
            float dval = 0.0f;
            if (tid == 0)       dval = build_entry_g<0>(alB, beB, gaB, Ap.A + AOFF0, 0);
            else if (tid < 10)  dval = build_entry_g<1>(alB, beB, gaB, Ap.A + AOFF1, tid - 1);
            else if (tid < 35)  dval = build_entry_g<2>(alB, beB, gaB, Ap.A + AOFF2, tid - 10);

            // pre-issue all 9 x loads (in flight across the barrier)
            float4 x0 = __ldcs(xp0 + lane);
            float4 xr1[3];
#pragma unroll
            for (int j = 0; j < 3; ++j) xr1[j] = __ldcs(xp1 + j * 32 + lane);
            float4 xr2[5];
#pragma unroll
            for (int j = 0; j < 5; ++j) xr2[j] = __ldcs(xp2 + j * 32 + lane);

            // publish into padded layout
            if (tid == 0) {
                DmS[0] = dval;
            } else if (tid < 10) {
                const int e = tid - 1, i = e / 3, j = e - i * 3;
                DmS[4 + i * 4 + j] = dval;
            } else if (tid < 35) {
                const int e = tid - 10, i = e / 5, j = e - i * 5;
                DmS[16 + i * 8 + j] = dval;
            }
            __syncthreads();

            {   // l=0
                float c = DmS[0];
                float4* yp0 = (float4*)(y + base0);
                float4 r = { c * x0.x, c * x0.y, c * x0.z, c * x0.w };
                __stcs(yp0 + lane, r);
            }
            {   // l=1 (row i at float4 index 1+i)
                float4* yp1 = (float4*)(y + base1);
#pragma unroll
                for (int i = 0; i < 3; ++i) {
                    float4 v0 = DmS4[1 + i];
                    float4 acc = { 0.f, 0.f, 0.f, 0.f };
#pragma unroll
                    for (int j = 0; j < 3; ++j) {
                        float c = comp4(v0, j);
                        acc.x = fmaf(c, xr1[j].x, acc.x);
                        acc.y = fmaf(c, xr1[j].y, acc.y);
                        acc.z = fmaf(c, xr1[j].z, acc.z);
                        acc.w = fmaf(c, xr1[j].w, acc.w);
                    }
                    __stcs(yp1 + i * 32 + lane, acc);
                }
            }
            {   // l=2 (row i at float4 indices 4+2i, 5+2i)
                float4* yp2 = (float4*)(y + base2);
#pragma unroll
                for (int i = 0; i < 5; ++i) {
                    float4 v0 = DmS4[4 + 2 * i];
                    float4 v1 = DmS4[5 + 2 * i];
                    float4 acc = { 0.f, 0.f, 0.f, 0.f };
#pragma unroll
                    for (int j = 0; j < 5; ++j) {
                        float c = (j < 4) ? comp4(v0, j) : v1.x;
                        acc.x = fmaf(c, xr2[j].x, acc.x);
                        acc.y = fmaf(c, xr2[j].y, acc.y);
                        acc.z = fmaf(c, xr2[j].z, acc.z);
                        acc.w = fmaf(c, xr2[j].w, acc.w);
                    }
                    __stcs(yp2 + i * 32 + lane, acc);
                }
            }
            break;
        }
        case 1: seg_full<3>(x, y, Ap.A + AOFF3, alB, beB, gaB, DmS, DmS4, b, 72,  tid); break;
        default: seg_full<4>(x, y, Ap.A + AOFF4, alB, beB, gaB, DmS, DmS4, b, 128, tid); break;
    }
}

// ---------------------------------------------------------------------------
extern "C" void kernel_launch(void* const* d_in, const int* in_sizes, int n_in,
                              void* d_out, int out_size) {
    (void)in_sizes; (void)n_in; (void)out_size;
    const float* x  = (const float*)d_in[0];  // (2048, 200, 128) f32
    const float* al = (const float*)d_in[1];  // (2048, 5, 2) f32
    const float* be = (const float*)d_in[2];
    const float* ga = (const float*)d_in[3];
    float* y = (float*)d_out;

    AParams P;
    host_compute_A(P);   // host-side, capture-time only

    fused_kernel<<<BATCH * 3, 256>>>(P, x, al, be, ga, y);
}